// round 5
// baseline (speedup 1.0000x reference)
#include <cuda_runtime.h>
#include <cstdint>

#define E_TOT   30000
#define NB      10
#define HID     16
#define WNUM    9216
#define EB      64
#define NTHR    256
#define INV_S3  0.5773502691896258f
#define PW0     0.10206207261596575f
#define PW1     0.17677669529663687f

typedef unsigned long long u64;

__device__ __forceinline__ u64 pk2(float lo, float hi) {
    u64 r; asm("mov.b64 %0, {%1,%2};" : "=l"(r) : "f"(lo), "f"(hi)); return r;
}
__device__ __forceinline__ void up2(u64 v, float& lo, float& hi) {
    asm("mov.b64 {%0,%1}, %2;" : "=f"(lo), "=f"(hi) : "l"(v));
}
__device__ __forceinline__ u64 fma2(u64 a, u64 b, u64 c) {
    u64 d; asm("fma.rn.f32x2 %0, %1, %2, %3;" : "=l"(d) : "l"(a), "l"(b), "l"(c)); return d;
}
__device__ __forceinline__ u64 mul2(u64 a, u64 b) {
    u64 d; asm("mul.rn.f32x2 %0, %1, %2;" : "=l"(d) : "l"(a), "l"(b)); return d;
}
__device__ __forceinline__ void cpa16(uint32_t s, const void* g) {
    asm volatile("cp.async.cg.shared.global [%0], [%1], 16;" :: "r"(s), "l"(g));
}
#define CP_COMMIT()  asm volatile("cp.async.commit_group;")
#define CP_WAIT(n)   asm volatile("cp.async.wait_group %0;" :: "n"(n))

// SMEM layout (float offsets), EB = 64:
//   hS  [16][64]      @ 0       (1024)
//   zA  [96][64]      @ 1024    (6144)  u<64: x0*sh0 ; u>=64: INV_S3*(x1.sh1)
//   zB  [64][64]      @ 7168    (4096)  x0
//   xc  [96][64]      @ 11264   (6144)  x1 rows u*3+m
//   sh0 [64]          @ 17408
//   sh1 [3][64]       @ 17472
//   w2s 2 x [17][4][64] @ 17664 (2*4352; phase B uses [17][4][32] prefix)
#define W2S_OFF     17664
#define CH_A        4352          // 17*4*64
#define CH_B        2176          // 17*4*32
#define SMEM_FLOATS (W2S_OFF + 2*CH_A)
#define SMEM_BYTES  (SMEM_FLOATS * 4)

extern __shared__ float smem[];

__global__ void __launch_bounds__(NTHR, 2) conv_fused_kernel(
    const float* __restrict__ x,   const float* __restrict__ rps,
    const float* __restrict__ dist,const float* __restrict__ freq,
    const float* __restrict__ w1,  const float* __restrict__ b1,
    const float* __restrict__ w2,  const float* __restrict__ b2,
    float* __restrict__ out)
{
    float* hS  = smem;
    float* zA  = smem + 1024;
    float* zB  = smem + 7168;
    float* xc  = smem + 11264;
    float* sh0 = smem + 17408;
    float* sh1 = smem + 17472;
    float* w2s = smem + W2S_OFF;

    const uint32_t w2s_s = (uint32_t)__cvta_generic_to_shared(w2s);

    const int t  = threadIdx.x;
    const int e0 = blockIdx.x * EB;

    // ---- async stagers: chunk = 4 consecutive u values ----
    auto stageA = [&](int sc, int buf) {
        uint32_t dst0 = w2s_s + (uint32_t)(buf * CH_A) * 4u;
        #pragma unroll
        for (int it = 0; it < 5; it++) {
            int q4 = t + it * NTHR;
            if (q4 < CH_A / 4) {
                int q = q4 * 4;
                int k = q >> 8;          // /256
                int r = q & 255;
                int u = r >> 6;
                int w = r & 63;
                int up = sc*4 + u;
                int j  = (up < 64) ? (up*64 + w) : (7168 + (up-64)*64 + w);
                const float* srcp = (k < 16) ? (w2 + k*WNUM + j) : (b2 + j);
                cpa16(dst0 + (uint32_t)q4 * 16u, srcp);
            }
        }
    };
    auto stageB = [&](int sc, int buf) {
        uint32_t dst0 = w2s_s + (uint32_t)(buf * CH_B) * 4u;
        #pragma unroll
        for (int it = 0; it < 3; it++) {
            int q4 = t + it * NTHR;
            if (q4 < CH_B / 4) {
                int q = q4 * 4;
                int k = q >> 7;          // /128
                int r = q & 127;
                int u = r >> 5;
                int w = r & 31;
                int up = sc*4 + u;
                int j  = (up < 64) ? (4096 + up*32 + w) : (6144 + (up-64)*32 + w);
                const float* srcp = (k < 16) ? (w2 + k*WNUM + j) : (b2 + j);
                cpa16(dst0 + (uint32_t)q4 * 16u, srcp);
            }
        }
    };

    // prefetch A-chunk 0 immediately — overlaps with all setup below
    stageA(0, 0);
    CP_COMMIT();

    // ---------------- setup: per-edge radial MLP + sh ----------------
    if (t < EB) {
        int e = e0 + t;
        if (e < E_TOT) {
            float d  = dist[e] * 0.25f;
            float id = 1.0f / d;
            float d2 = d * d;
            float d5 = d2 * d2 * d;
            float env = id - 28.0f*d5 + 48.0f*d5*d - 21.0f*d5*d2;
            env = (d < 1.0f) ? env : 0.0f;
            float basis[NB];
            #pragma unroll
            for (int i = 0; i < NB; i++) basis[i] = env * sinf(freq[i] * d);
            #pragma unroll
            for (int k = 0; k < HID; k++) {
                float pre = b1[k];
                #pragma unroll
                for (int i = 0; i < NB; i++) pre = fmaf(basis[i], w1[i*HID + k], pre);
                float s = 1.0f / (1.0f + expf(-pre));
                hS[k*EB + t] = pre * s;
            }
            sh0[t]        = rps[e*4 + 0];
            sh1[0*EB + t] = rps[e*4 + 1];
            sh1[1*EB + t] = rps[e*4 + 2];
            sh1[2*EB + t] = rps[e*4 + 3];
        } else {
            #pragma unroll
            for (int k = 0; k < HID; k++) hS[k*EB + t] = 0.0f;
            sh0[t] = 0.0f; sh1[t] = 0.0f; sh1[EB + t] = 0.0f; sh1[2*EB + t] = 0.0f;
        }
    }
    __syncthreads();

    // ---------------- setup: x tiles ----------------
    for (int idx = t; idx < EB*160; idx += NTHR) {
        int el = idx / 160, c = idx - el*160;
        int e  = e0 + el;
        float v = (e < E_TOT) ? x[e*160 + c] : 0.0f;
        if (c < 64) {
            zB[c*EB + el] = v;
            zA[c*EB + el] = v * sh0[el];
        } else {
            xc[(c-64)*EB + el] = v;
        }
    }
    __syncthreads();
    for (int idx = t; idx < 32*EB; idx += NTHR) {
        int u = idx / EB, el = idx % EB;
        float a = xc[(u*3+0)*EB+el]*sh1[0*EB+el]
                + xc[(u*3+1)*EB+el]*sh1[1*EB+el]
                + xc[(u*3+2)*EB+el]*sh1[2*EB+el];
        zA[(64+u)*EB + el] = INV_S3 * a;
    }

    // ---------------- Phase A: out0 (Wa + Wd), 64 output cols ----------------
    {
        const int tw = t & 63;
        const int tg = t >> 6;                    // 4 groups x 16 edges (8 pairs)
        const int eb = tg * 16;                   // edge base within block
        u64 acc[8] = {0,0,0,0,0,0,0,0};

        for (int sc = 0; sc < 24; sc++) {
            if (sc + 1 < 24) {
                stageA(sc + 1, (sc + 1) & 1);
                CP_COMMIT();
                CP_WAIT(1);
            } else {
                CP_WAIT(0);
            }
            __syncthreads();
            const float* wb = w2s + (sc & 1) * CH_A;

            u64 wgt[8][4];
            // k = 0 : multiply
            {
                u64 hv[8];
                #pragma unroll
                for (int p = 0; p < 8; p++)
                    hv[p] = *(const u64*)&hS[eb + 2*p];
                #pragma unroll
                for (int u = 0; u < 4; u++) {
                    float wv = wb[u*64 + tw];
                    u64 wv2 = pk2(wv, wv);
                    #pragma unroll
                    for (int p = 0; p < 8; p++)
                        wgt[p][u] = mul2(hv[p], wv2);
                }
            }
            #pragma unroll
            for (int k = 1; k < 16; k++) {
                u64 hv[8];
                #pragma unroll
                for (int p = 0; p < 8; p++)
                    hv[p] = *(const u64*)&hS[k*EB + eb + 2*p];
                #pragma unroll
                for (int u = 0; u < 4; u++) {
                    float wv = wb[(k*4 + u)*64 + tw];
                    u64 wv2 = pk2(wv, wv);
                    #pragma unroll
                    for (int p = 0; p < 8; p++)
                        wgt[p][u] = fma2(hv[p], wv2, wgt[p][u]);
                }
            }
            // TP + bias fold
            #pragma unroll
            for (int u = 0; u < 4; u++) {
                float b = wb[(16*4 + u)*64 + tw];
                u64 bb = pk2(b, b);
                int ug = sc*4 + u;
                #pragma unroll
                for (int p = 0; p < 8; p++) {
                    u64 zv = *(const u64*)&zA[ug*EB + eb + 2*p];
                    acc[p] = fma2(wgt[p][u], zv, acc[p]);
                    acc[p] = fma2(bb, zv, acc[p]);
                }
            }
            __syncthreads();
        }
        #pragma unroll
        for (int p = 0; p < 8; p++) {
            float lo, hi; up2(acc[p], lo, hi);
            int eA = e0 + eb + 2*p;
            if (eA     < E_TOT) out[(size_t)eA*160 + tw]     = PW0 * lo;
            if (eA + 1 < E_TOT) out[(size_t)(eA+1)*160 + tw] = PW0 * hi;
        }
    }

    // ---------------- Phase B: out1 (Wb + Wc), 32 cols x 3 ----------------
    {
        const int tw2 = t & 31;
        const int tg2 = t >> 5;                   // 8 groups x 8 edges (4 pairs)
        const int eb2 = tg2 * 8;
        u64 pb[4]    = {0,0,0,0};
        u64 pc[4][3] = {{0,0,0},{0,0,0},{0,0,0},{0,0,0}};

        stageB(0, 0);
        CP_COMMIT();

        for (int sc = 0; sc < 24; sc++) {
            if (sc + 1 < 24) {
                stageB(sc + 1, (sc + 1) & 1);
                CP_COMMIT();
                CP_WAIT(1);
            } else {
                CP_WAIT(0);
            }
            __syncthreads();
            const float* wb = w2s + (sc & 1) * CH_B;

            u64 wgt[4][4];
            {
                u64 hv[4];
                #pragma unroll
                for (int p = 0; p < 4; p++)
                    hv[p] = *(const u64*)&hS[eb2 + 2*p];
                #pragma unroll
                for (int u = 0; u < 4; u++) {
                    float wv = wb[u*32 + tw2];
                    u64 wv2 = pk2(wv, wv);
                    #pragma unroll
                    for (int p = 0; p < 4; p++)
                        wgt[p][u] = mul2(hv[p], wv2);
                }
            }
            #pragma unroll
            for (int k = 1; k < 16; k++) {
                u64 hv[4];
                #pragma unroll
                for (int p = 0; p < 4; p++)
                    hv[p] = *(const u64*)&hS[k*EB + eb2 + 2*p];
                #pragma unroll
                for (int u = 0; u < 4; u++) {
                    float wv = wb[(k*4 + u)*32 + tw2];
                    u64 wv2 = pk2(wv, wv);
                    #pragma unroll
                    for (int p = 0; p < 4; p++)
                        wgt[p][u] = fma2(hv[p], wv2, wgt[p][u]);
                }
            }
            if (sc < 16) {
                #pragma unroll
                for (int u = 0; u < 4; u++) {
                    float b = wb[(16*4 + u)*32 + tw2];
                    u64 bb = pk2(b, b);
                    int ug = sc*4 + u;
                    #pragma unroll
                    for (int p = 0; p < 4; p++) {
                        u64 zv = *(const u64*)&zB[ug*EB + eb2 + 2*p];
                        pb[p] = fma2(wgt[p][u], zv, pb[p]);
                        pb[p] = fma2(bb, zv, pb[p]);
                    }
                }
            } else {
                #pragma unroll
                for (int u = 0; u < 4; u++) {
                    float b = wb[(16*4 + u)*32 + tw2];
                    u64 bb = pk2(b, b);
                    int u1 = (sc - 16)*4 + u;
                    #pragma unroll
                    for (int m = 0; m < 3; m++) {
                        #pragma unroll
                        for (int p = 0; p < 4; p++) {
                            u64 xv = *(const u64*)&xc[(u1*3+m)*EB + eb2 + 2*p];
                            pc[p][m] = fma2(wgt[p][u], xv, pc[p][m]);
                            pc[p][m] = fma2(bb, xv, pc[p][m]);
                        }
                    }
                }
            }
            __syncthreads();
        }
        #pragma unroll
        for (int p = 0; p < 4; p++) {
            float pbl, pbh; up2(pb[p], pbl, pbh);
            float pcl[3], pch[3];
            #pragma unroll
            for (int m = 0; m < 3; m++) up2(pc[p][m], pcl[m], pch[m]);
            int el = eb2 + 2*p;
            int e  = e0 + el;
            float s0l = sh0[el], s0h = sh0[el+1];
            if (e < E_TOT) {
                #pragma unroll
                for (int m = 0; m < 3; m++)
                    out[(size_t)e*160 + 64 + tw2*3 + m] =
                        (PW1*INV_S3) * (pbl*sh1[m*EB + el] + pcl[m]*s0l);
            }
            if (e + 1 < E_TOT) {
                #pragma unroll
                for (int m = 0; m < 3; m++)
                    out[(size_t)(e+1)*160 + 64 + tw2*3 + m] =
                        (PW1*INV_S3) * (pbh*sh1[m*EB + el + 1] + pch[m]*s0h);
            }
        }
    }
}

extern "C" void kernel_launch(void* const* d_in, const int* in_sizes, int n_in,
                              void* d_out, int out_size) {
    (void)in_sizes; (void)n_in; (void)out_size;
    const float* x    = (const float*)d_in[0];
    const float* rps  = (const float*)d_in[1];
    const float* dist = (const float*)d_in[2];
    const float* freq = (const float*)d_in[3];
    const float* w1   = (const float*)d_in[4];
    const float* b1   = (const float*)d_in[5];
    const float* w2   = (const float*)d_in[6];
    const float* b2   = (const float*)d_in[7];
    float* out = (float*)d_out;

    cudaFuncSetAttribute(conv_fused_kernel,
                         cudaFuncAttributeMaxDynamicSharedMemorySize, SMEM_BYTES);

    const int nblocks = (E_TOT + EB - 1) / EB;   // 469
    conv_fused_kernel<<<nblocks, NTHR, SMEM_BYTES>>>(
        x, rps, dist, freq, w1, b1, w2, b2, out);
}

// round 7
// speedup vs baseline: 2.3298x; 2.3298x over previous
#include <cuda_runtime.h>
#include <cstdint>

#define E_TOT   30000
#define NB      10
#define WNUM    9216
#define EB      128
#define NTHR    256
#define INV_S3  0.5773502691896258f
#define PW0     0.10206207261596575f
#define PW1     0.17677669529663687f
#define PW1S    (PW1 * INV_S3)

// Chunk inventory: 102 chunks of K=32, consumed in order.
//  seg0: j=0 (v=x0[0:32],  A=hp*F) B1 N=64   chunks [0,17)
//  seg1: j=1 (v=x0[32:64], A=hp*F) B1 N=64   chunks [17,34)
//  seg2: j=2 (v=zAd,       A=h *F) B1 N=64   chunks [34,51)
//  seg3: j=0 (x0[0:32],    A=h *F) B2 N=32   chunks [51,68)
//  seg4: j=1 (x0[32:64],   A=h *F) B2 N=32   chunks [68,85)
//  seg5: m-triple (xc[:,m], A=h*F) B3 N=32   chunks [85,102)
#define NCH 102

__device__ float g_B1[51 * 2048];   // N=64 chunks, fragment-ordered
__device__ float g_B2[34 * 1024];   // N=32 chunks
__device__ float g_B3[17 * 1024];   // N=32 chunks (shared across m)

// SMEM float offsets
#define OFF_H    0        // [17][128]  h   (k=16 -> 1)
#define OFF_HP   2176     // [17][128]  h*sh0 (k=16 -> sh0)
#define OFF_X0   4352     // [64][129]
#define OFF_ZAD  12608    // [32][129]
#define OFF_XC   16736    // [96][129]  rows u*3+m
#define OFF_SH0  29120    // [128]
#define OFF_SH1  29248    // [3][128]
#define OFF_BB   29632    // 2 x 2048 B staging
#define SMEM_FL  33728
#define SMEM_BYTES (SMEM_FL * 4)

__device__ __forceinline__ float tf32r(float v) {
    uint32_t r; asm("cvt.rna.tf32.f32 %0, %1;" : "=r"(r) : "f"(v));
    return __uint_as_float(r);
}
__device__ __forceinline__ uint32_t tf32u(float v) {
    uint32_t r; asm("cvt.rna.tf32.f32 %0, %1;" : "=r"(r) : "f"(v));
    return r;
}
__device__ __forceinline__ uint32_t smem_u32(const void* p) {
    uint32_t a;
    asm("{ .reg .u64 t; cvta.to.shared.u64 t, %1; cvt.u32.u64 %0, t; }" : "=r"(a) : "l"(p));
    return a;
}
__device__ __forceinline__ void cpa16(uint32_t s, const void* g) {
    asm volatile("cp.async.cg.shared.global [%0], [%1], 16;" :: "r"(s), "l"(g));
}
#define CP_COMMIT() asm volatile("cp.async.commit_group;")
#define CP_WAIT0()  asm volatile("cp.async.wait_group 0;")

__device__ __forceinline__ void mma8(float (&d)[4], const uint32_t (&a)[4],
                                     uint32_t b0, uint32_t b1) {
    asm volatile(
        "mma.sync.aligned.m16n8k8.row.col.f32.tf32.tf32.f32 "
        "{%0,%1,%2,%3}, {%4,%5,%6,%7}, {%8,%9}, {%0,%1,%2,%3};"
        : "+f"(d[0]), "+f"(d[1]), "+f"(d[2]), "+f"(d[3])
        : "r"(a[0]), "r"(a[1]), "r"(a[2]), "r"(a[3]), "r"(b0), "r"(b1));
}

// ---------------------------------------------------------------------------
// Prep: gather w2/b2 into fragment-ordered, tf32-rounded chunks.
// Within a chunk, element index = ((ks*NT + nt)*32 + lane)*2 + p
//   k_in_chunk = ks*8 + (lane&3) + p*4 ;  n = nt*8 + (lane>>2)
// ---------------------------------------------------------------------------
__global__ void prep_kernel(const float* __restrict__ w2, const float* __restrict__ b2) {
    int i = blockIdx.x * 256 + threadIdx.x;
    if (i < 51 * 2048) {                       // B1 (NT=8, N=64)
        int c = i >> 11, w = i & 2047;
        int lane = (w >> 1) & 31, p = w & 1, q = w >> 6;
        int ks = q >> 3, nt = q & 7;
        int j = c / 17, k = c % 17;
        int kk = ks * 8 + (lane & 3) + p * 4;
        int n  = nt * 8 + (lane >> 2);
        int col = (j < 2) ? ((j * 32 + kk) * 64 + n) : (7168 + kk * 64 + n);
        float val = (k < 16) ? w2[k * WNUM + col] : b2[col];
        g_B1[c * 2048 + w] = tf32r(val);
        return;
    }
    i -= 51 * 2048;
    if (i < 34 * 1024) {                       // B2 (NT=4, N=32)
        int c = i >> 10, w = i & 1023;
        int lane = (w >> 1) & 31, p = w & 1, q = w >> 6;
        int ks = q >> 2, nt = q & 3;
        int j = c / 17, k = c % 17;
        int kk = ks * 8 + (lane & 3) + p * 4;
        int n  = nt * 8 + (lane >> 2);
        int col = 4096 + (j * 32 + kk) * 32 + n;
        float val = (k < 16) ? w2[k * WNUM + col] : b2[col];
        g_B2[c * 1024 + w] = tf32r(val);
        return;
    }
    i -= 34 * 1024;
    if (i < 17 * 1024) {                       // B3 (NT=4, N=32)
        int c = i >> 10, w = i & 1023;
        int lane = (w >> 1) & 31, p = w & 1, q = w >> 6;
        int ks = q >> 2, nt = q & 3;
        int k = c;
        int kk = ks * 8 + (lane & 3) + p * 4;
        int n  = nt * 8 + (lane >> 2);
        int col = 6144 + kk * 32 + n;
        float val = (k < 16) ? w2[k * WNUM + col] : b2[col];
        g_B3[c * 1024 + w] = tf32r(val);
    }
}

// ---------------------------------------------------------------------------
// Main kernel
// ---------------------------------------------------------------------------
__device__ __forceinline__ const float* chunk_src(int c, int& nfl) {
    if (c < 51) { nfl = 2048; return g_B1 + c * 2048; }
    if (c < 85) { nfl = 1024; return g_B2 + (c - 51) * 1024; }
    nfl = 1024; return g_B3 + (c - 85) * 1024;
}

__device__ __forceinline__ void stage_chunk(int c, uint32_t sbB, int t) {
    int nfl; const float* src = chunk_src(c, nfl);
    uint32_t dst = sbB + (uint32_t)((c & 1) * 2048) * 4u;
    int units = nfl / 4;
    for (int u = t; u < units; u += NTHR)
        cpa16(dst + (uint32_t)u * 16u, src + u * 4);
    CP_COMMIT();
}

template<int NT>
__device__ __forceinline__ void run_seg(
    int cbase, const float* __restrict__ hb,
    const float* __restrict__ fb, int fstride,
    float (&acc)[NT][4],
    int eb, int lane, int t,
    const float* __restrict__ smemf, uint32_t sbB)
{
    const int r0 = lane >> 2, c0 = lane & 3;
    float Ff[4][4];
    #pragma unroll
    for (int ks = 0; ks < 4; ks++) {
        int v0 = ks * 8 + c0;
        Ff[ks][0] = fb[v0 * fstride + eb + r0];
        Ff[ks][1] = fb[v0 * fstride + eb + r0 + 8];
        Ff[ks][2] = fb[(v0 + 4) * fstride + eb + r0];
        Ff[ks][3] = fb[(v0 + 4) * fstride + eb + r0 + 8];
    }
    for (int k = 0; k < 17; k++) {
        int c = cbase + k;
        CP_WAIT0();
        __syncthreads();
        if (c + 1 < NCH) stage_chunk(c + 1, sbB, t);
        const float* Bb = smemf + OFF_BB + (c & 1) * 2048;
        float h0 = hb[k * 128 + eb + r0];
        float h1 = hb[k * 128 + eb + r0 + 8];
        uint32_t a[4][4];
        #pragma unroll
        for (int ks = 0; ks < 4; ks++) {
            a[ks][0] = tf32u(h0 * Ff[ks][0]);
            a[ks][1] = tf32u(h1 * Ff[ks][1]);
            a[ks][2] = tf32u(h0 * Ff[ks][2]);
            a[ks][3] = tf32u(h1 * Ff[ks][3]);
        }
        #pragma unroll
        for (int nt = 0; nt < NT; nt++) {
            #pragma unroll
            for (int ks = 0; ks < 4; ks++) {
                float2 bv = *(const float2*)&Bb[(((ks * NT + nt) * 32) + lane) * 2];
                mma8(acc[nt], a[ks], __float_as_uint(bv.x), __float_as_uint(bv.y));
            }
        }
    }
}

__device__ __forceinline__ void run_seg3(
    int cbase, const float* __restrict__ hb,
    const float* __restrict__ xcb,
    float (&pc)[3][4][4],
    int eb, int lane, int t,
    const float* __restrict__ smemf, uint32_t sbB)
{
    const int r0 = lane >> 2, c0 = lane & 3;
    float Ff[3][4][4];
    #pragma unroll
    for (int m = 0; m < 3; m++) {
        const float* fb = xcb + m * 129;           // stride 3*129 in u
        #pragma unroll
        for (int ks = 0; ks < 4; ks++) {
            int v0 = ks * 8 + c0;
            Ff[m][ks][0] = fb[v0 * 387 + eb + r0];
            Ff[m][ks][1] = fb[v0 * 387 + eb + r0 + 8];
            Ff[m][ks][2] = fb[(v0 + 4) * 387 + eb + r0];
            Ff[m][ks][3] = fb[(v0 + 4) * 387 + eb + r0 + 8];
        }
    }
    for (int k = 0; k < 17; k++) {
        int c = cbase + k;
        CP_WAIT0();
        __syncthreads();
        if (c + 1 < NCH) stage_chunk(c + 1, sbB, t);
        const float* Bb = smemf + OFF_BB + (c & 1) * 2048;
        float h0 = hb[k * 128 + eb + r0];
        float h1 = hb[k * 128 + eb + r0 + 8];
        uint32_t a[3][4][4];
        #pragma unroll
        for (int m = 0; m < 3; m++) {
            #pragma unroll
            for (int ks = 0; ks < 4; ks++) {
                a[m][ks][0] = tf32u(h0 * Ff[m][ks][0]);
                a[m][ks][1] = tf32u(h1 * Ff[m][ks][1]);
                a[m][ks][2] = tf32u(h0 * Ff[m][ks][2]);
                a[m][ks][3] = tf32u(h1 * Ff[m][ks][3]);
            }
        }
        #pragma unroll
        for (int nt = 0; nt < 4; nt++) {
            #pragma unroll
            for (int ks = 0; ks < 4; ks++) {
                float2 bv = *(const float2*)&Bb[(((ks * 4 + nt) * 32) + lane) * 2];
                uint32_t b0 = __float_as_uint(bv.x), b1 = __float_as_uint(bv.y);
                #pragma unroll
                for (int m = 0; m < 3; m++)
                    mma8(pc[m][nt], a[m][ks], b0, b1);
            }
        }
    }
}

extern __shared__ float smem[];

__global__ void __launch_bounds__(NTHR, 1) conv_mma_kernel(
    const float* __restrict__ x,    const float* __restrict__ rps,
    const float* __restrict__ dist, const float* __restrict__ freq,
    const float* __restrict__ w1,   const float* __restrict__ b1,
    float* __restrict__ out)
{
    const int t    = threadIdx.x;
    const int wid  = t >> 5;
    const int lane = t & 31;
    const int e0   = blockIdx.x * EB;
    const int eb   = wid * 16;
    const uint32_t sbB = smem_u32(smem) + OFF_BB * 4;

    // prefetch chunk 0 — overlaps setup
    stage_chunk(0, sbB, t);

    // --- setup: radial MLP + sh ---
    if (t < EB) {
        int e = e0 + t;
        if (e < E_TOT) {
            float d  = dist[e] * 0.25f;
            float id = 1.0f / d;
            float d2 = d * d;
            float d5 = d2 * d2 * d;
            float env = id - 28.0f * d5 + 48.0f * d5 * d - 21.0f * d5 * d2;
            env = (d < 1.0f) ? env : 0.0f;
            float basis[NB];
            #pragma unroll
            for (int i = 0; i < NB; i++) basis[i] = env * sinf(freq[i] * d);
            float s0 = rps[e * 4 + 0];
            smem[OFF_SH0 + t]           = s0;
            smem[OFF_SH1 + 0 * 128 + t] = rps[e * 4 + 1];
            smem[OFF_SH1 + 1 * 128 + t] = rps[e * 4 + 2];
            smem[OFF_SH1 + 2 * 128 + t] = rps[e * 4 + 3];
            #pragma unroll
            for (int k = 0; k < 16; k++) {
                float pre = b1[k];
                #pragma unroll
                for (int i = 0; i < NB; i++) pre = fmaf(basis[i], w1[i * 16 + k], pre);
                float sg = 1.0f / (1.0f + expf(-pre));
                float hv = pre * sg;
                smem[OFF_H  + k * 128 + t] = hv;
                smem[OFF_HP + k * 128 + t] = hv * s0;
            }
            smem[OFF_H  + 16 * 128 + t] = 1.0f;
            smem[OFF_HP + 16 * 128 + t] = s0;
        } else {
            #pragma unroll
            for (int k = 0; k < 17; k++) {
                smem[OFF_H  + k * 128 + t] = 0.0f;
                smem[OFF_HP + k * 128 + t] = 0.0f;
            }
            smem[OFF_SH0 + t] = 0.0f;
            smem[OFF_SH1 + 0 * 128 + t] = 0.0f;
            smem[OFF_SH1 + 1 * 128 + t] = 0.0f;
            smem[OFF_SH1 + 2 * 128 + t] = 0.0f;
        }
    }

    // --- x tiles (transposed, stride 129) ---
    for (int idx = t; idx < EB * 40; idx += NTHR) {
        int el = idx / 40, c4 = idx - el * 40;
        int e  = e0 + el;
        float4 v = make_float4(0.f, 0.f, 0.f, 0.f);
        if (e < E_TOT) v = *(const float4*)&x[(size_t)e * 160 + c4 * 4];
        if (c4 < 16) {
            int vb = c4 * 4;
            smem[OFF_X0 + (vb + 0) * 129 + el] = v.x;
            smem[OFF_X0 + (vb + 1) * 129 + el] = v.y;
            smem[OFF_X0 + (vb + 2) * 129 + el] = v.z;
            smem[OFF_X0 + (vb + 3) * 129 + el] = v.w;
        } else {
            int vb = c4 * 4 - 64;
            smem[OFF_XC + (vb + 0) * 129 + el] = v.x;
            smem[OFF_XC + (vb + 1) * 129 + el] = v.y;
            smem[OFF_XC + (vb + 2) * 129 + el] = v.z;
            smem[OFF_XC + (vb + 3) * 129 + el] = v.w;
        }
    }
    __syncthreads();

    for (int idx = t; idx < 32 * 128; idx += NTHR) {
        int u = idx >> 7, el = idx & 127;
        float a = smem[OFF_XC + (u * 3 + 0) * 129 + el] * smem[OFF_SH1 + 0 * 128 + el]
                + smem[OFF_XC + (u * 3 + 1) * 129 + el] * smem[OFF_SH1 + 1 * 128 + el]
                + smem[OFF_XC + (u * 3 + 2) * 129 + el] * smem[OFF_SH1 + 2 * 128 + el];
        smem[OFF_ZAD + u * 129 + el] = INV_S3 * a;
    }
    __syncthreads();

    // --- accumulators ---
    float acc1[8][4];
    float acc2[4][4];
    float pc[3][4][4];
    #pragma unroll
    for (int i = 0; i < 8; i++) { acc1[i][0]=acc1[i][1]=acc1[i][2]=acc1[i][3]=0.f; }
    #pragma unroll
    for (int i = 0; i < 4; i++) { acc2[i][0]=acc2[i][1]=acc2[i][2]=acc2[i][3]=0.f; }
    #pragma unroll
    for (int m = 0; m < 3; m++)
        #pragma unroll
        for (int i = 0; i < 4; i++) { pc[m][i][0]=pc[m][i][1]=pc[m][i][2]=pc[m][i][3]=0.f; }

    run_seg<8>(0,  smem + OFF_HP, smem + OFF_X0,            129, acc1, eb, lane, t, smem, sbB);
    run_seg<8>(17, smem + OFF_HP, smem + OFF_X0 + 32 * 129, 129, acc1, eb, lane, t, smem, sbB);
    run_seg<8>(34, smem + OFF_H,  smem + OFF_ZAD,           129, acc1, eb, lane, t, smem, sbB);
    run_seg<4>(51, smem + OFF_H,  smem + OFF_X0,            129, acc2, eb, lane, t, smem, sbB);
    run_seg<4>(68, smem + OFF_H,  smem + OFF_X0 + 32 * 129, 129, acc2, eb, lane, t, smem, sbB);
    run_seg3 (85, smem + OFF_H,   smem + OFF_XC,                 pc,   eb, lane, t, smem, sbB);

    // --- epilogue (registers -> gmem) ---
    const int r0 = lane >> 2, cpair = 2 * (lane & 3);

    #pragma unroll
    for (int nt = 0; nt < 8; nt++) {
        int col = nt * 8 + cpair;
        int eA = e0 + eb + r0;
        if (eA < E_TOT) {
            float2 v = make_float2(PW0 * acc1[nt][0], PW0 * acc1[nt][1]);
            *(float2*)&out[(size_t)eA * 160 + col] = v;
        }
        int eB = eA + 8;
        if (eB < E_TOT) {
            float2 v = make_float2(PW0 * acc1[nt][2], PW0 * acc1[nt][3]);
            *(float2*)&out[(size_t)eB * 160 + col] = v;
        }
    }

    #pragma unroll
    for (int nt = 0; nt < 4; nt++) {
        int w0 = nt * 8 + cpair;
        #pragma unroll
        for (int half = 0; half < 2; half++) {
            int el = eb + r0 + half * 8;
            int e  = e0 + el;
            if (e >= E_TOT) continue;
            float s0v = smem[OFF_SH0 + el];
            float s1v[3];
            #pragma unroll
            for (int m = 0; m < 3; m++) s1v[m] = smem[OFF_SH1 + m * 128 + el];
            float pb0 = acc2[nt][half * 2 + 0];
            float pb1 = acc2[nt][half * 2 + 1];
            float vals[6];
            #pragma unroll
            for (int m = 0; m < 3; m++) {
                vals[m]     = PW1S * (pb0 * s1v[m] + pc[m][nt][half * 2 + 0] * s0v);
                vals[3 + m] = PW1S * (pb1 * s1v[m] + pc[m][nt][half * 2 + 1] * s0v);
            }
            size_t base = (size_t)e * 160 + 64 + 3 * w0;
            *(float2*)&out[base + 0] = make_float2(vals[0], vals[1]);
            *(float2*)&out[base + 2] = make_float2(vals[2], vals[3]);
            *(float2*)&out[base + 4] = make_float2(vals[4], vals[5]);
        }
    }
}

extern "C" void kernel_launch(void* const* d_in, const int* in_sizes, int n_in,
                              void* d_out, int out_size) {
    (void)in_sizes; (void)n_in; (void)out_size;
    const float* x    = (const float*)d_in[0];
    const float* rps  = (const float*)d_in[1];
    const float* dist = (const float*)d_in[2];
    const float* freq = (const float*)d_in[3];
    const float* w1   = (const float*)d_in[4];
    const float* b1   = (const float*)d_in[5];
    const float* w2   = (const float*)d_in[6];
    const float* b2   = (const float*)d_in[7];
    float* out = (float*)d_out;

    const int tot = 51 * 2048 + 34 * 1024 + 17 * 1024;
    prep_kernel<<<(tot + 255) / 256, 256>>>(w2, b2);

    cudaFuncSetAttribute(conv_mma_kernel,
                         cudaFuncAttributeMaxDynamicSharedMemorySize, SMEM_BYTES);
    const int nblocks = (E_TOT + EB - 1) / EB;   // 235
    conv_mma_kernel<<<nblocks, NTHR, SMEM_BYTES>>>(x, rps, dist, freq, w1, b1, out);
}